// round 2
// baseline (speedup 1.0000x reference)
#include <cuda_runtime.h>

// Problem constants
#define NN 2048   // layer size
#define RR 4      // displacement rank
#define BB 4096   // batch

// Scratch (device globals -- no allocation allowed in kernel_launch)
__device__ float g_P[NN * NN];   // g_P[c*NN + d] = T[d,c] = prefix along diagonal d up to col c
__device__ float g_Mt[NN * NN];  // g_Mt[c*NN + a] = M[a][c]   (K-major for GEMM B operand)

// ---------------------------------------------------------------------------
// Kernel 1: diagonal prefix scan.
// T[d,c] = sum_{m<=c} sum_i G[i][(d+m)%n] * H[i][m]
// One thread per diagonal d. H reads broadcast within a warp, G reads coalesced
// (consecutive d -> consecutive addresses). Stores transposed (g_P[c][d]) so
// stores are coalesced.
// ---------------------------------------------------------------------------
__global__ void scan_kernel(const float* __restrict__ G, const float* __restrict__ H) {
    const int d = blockIdx.x * blockDim.x + threadIdx.x;  // 0..NN-1
    float acc = 0.0f;
#pragma unroll 4
    for (int c = 0; c < NN; ++c) {
        const int s = (d + c) & (NN - 1);
        float v = __ldg(&G[0 * NN + s]) * __ldg(&H[0 * NN + c]);
        v = fmaf(__ldg(&G[1 * NN + s]), __ldg(&H[1 * NN + c]), v);
        v = fmaf(__ldg(&G[2 * NN + s]), __ldg(&H[2 * NN + c]), v);
        v = fmaf(__ldg(&G[3 * NN + s]), __ldg(&H[3 * NN + c]), v);
        acc += v;
        g_P[c * NN + d] = acc;
    }
}

// ---------------------------------------------------------------------------
// Kernel 2: assemble Mt[c][a] = M[a][c] = 2*T[d,c] - T[d,n-1],  d=(a-c) mod n
// Threads along a: P reads coalesced (consecutive a -> consecutive d),
// Mt writes coalesced.
// ---------------------------------------------------------------------------
__global__ void build_mt_kernel() {
    const int a = blockIdx.x * blockDim.x + threadIdx.x;
    const int c = blockIdx.y;
    const int d = (a - c) & (NN - 1);
    g_Mt[c * NN + a] = 2.0f * g_P[c * NN + d] - g_P[(NN - 1) * NN + d];
}

// ---------------------------------------------------------------------------
// Kernel 3: SGEMM  C(BB x NN) = A(BB x NN) * g_Mt(NN x NN)
// Classic 128x128x16 tiling, 256 threads, 8x8 per-thread microtile, fp32.
// B operand (g_Mt) is referenced as a device global INSIDE the kernel --
// passing a __device__ symbol as a host-side kernel arg was the R1 bug.
// ---------------------------------------------------------------------------
__global__ __launch_bounds__(256, 2)
void sgemm_kernel(const float* __restrict__ A, float* __restrict__ C) {
    constexpr int BM = 128, BN = 128, BK = 16;
    const int K = NN, Nn = NN;
    const float* __restrict__ Bm = g_Mt;   // device-side symbol reference (valid)

    __shared__ float As[BK][BM + 4];  // padded to soften transpose-store conflicts
    __shared__ float Bs[BK][BN];

    const int tid = threadIdx.x;          // 0..255
    const int tx = tid & 15;              // 0..15 -> N direction
    const int ty = tid >> 4;              // 0..15 -> M direction
    const int m0 = blockIdx.y * BM;
    const int n0 = blockIdx.x * BN;

    // A-tile loader coords: 64 rows x 16 cols per pass (2 passes)
    const int a_row = tid >> 2;           // 0..63
    const int a_col = (tid & 3) * 4;      // 0,4,8,12
    // B-tile loader coords: 8 rows x 128 cols per pass (2 passes)
    const int b_row = tid >> 5;           // 0..7
    const int b_col = (tid & 31) * 4;     // 0..124

    float acc[8][8] = {};

    for (int k0 = 0; k0 < K; k0 += BK) {
#pragma unroll
        for (int p = 0; p < 2; ++p) {
            const int r = a_row + p * 64;
            float4 v = *reinterpret_cast<const float4*>(&A[(m0 + r) * K + k0 + a_col]);
            As[a_col + 0][r] = v.x;
            As[a_col + 1][r] = v.y;
            As[a_col + 2][r] = v.z;
            As[a_col + 3][r] = v.w;
        }
#pragma unroll
        for (int p = 0; p < 2; ++p) {
            const int r = b_row + p * 8;
            float4 v = *reinterpret_cast<const float4*>(&Bm[(k0 + r) * Nn + n0 + b_col]);
            *reinterpret_cast<float4*>(&Bs[r][b_col]) = v;
        }
        __syncthreads();

#pragma unroll
        for (int k = 0; k < BK; ++k) {
            float ar[8], br[8];
#pragma unroll
            for (int i = 0; i < 8; ++i) ar[i] = As[k][ty * 8 + i];
#pragma unroll
            for (int j = 0; j < 8; ++j) br[j] = Bs[k][tx * 8 + j];
#pragma unroll
            for (int i = 0; i < 8; ++i)
#pragma unroll
                for (int j = 0; j < 8; ++j)
                    acc[i][j] = fmaf(ar[i], br[j], acc[i][j]);
        }
        __syncthreads();
    }

#pragma unroll
    for (int i = 0; i < 8; ++i) {
#pragma unroll
        for (int j = 0; j < 8; j += 4) {
            float4 v = make_float4(acc[i][j], acc[i][j + 1], acc[i][j + 2], acc[i][j + 3]);
            *reinterpret_cast<float4*>(&C[(m0 + ty * 8 + i) * Nn + n0 + tx * 8 + j]) = v;
        }
    }
}

// ---------------------------------------------------------------------------
extern "C" void kernel_launch(void* const* d_in, const int* in_sizes, int n_in,
                              void* d_out, int out_size) {
    const float* x = (const float*)d_in[0];  // (BB, NN)
    const float* G = (const float*)d_in[1];  // (RR, NN)
    const float* H = (const float*)d_in[2];  // (RR, NN)
    float* out = (float*)d_out;              // (BB, NN)

    scan_kernel<<<NN / 128, 128>>>(G, H);
    build_mt_kernel<<<dim3(NN / 128, NN), 128>>>();
    sgemm_kernel<<<dim3(NN / 128, BB / 128), 256>>>(x, out);
}

// round 4
// speedup vs baseline: 2.1188x; 2.1188x over previous
#include <cuda_runtime.h>
#include <cuda_bf16.h>
#include <cstdint>

// Problem constants
#define NN 2048
#define RR 4
#define BB 4096
#define NSEG 16
#define SEGLEN (NN / NSEG)

// GEMM tiling
#define BM 128
#define BN 128
#define BKK 64                   // K elems per chunk (bf16)
#define NCH (NN / BKK)           // 32 chunks
#define SSTRIDE 72               // smem row stride in bf16 (64 data + 8 pad) = 144B
#define ROWB (SSTRIDE * 2)       // 144 bytes, 16B-aligned, conflict-free for ldmatrix
#define TILEB (128 * ROWB)       // 18432 B per operand tile
#define STAGEB (4 * TILEB)       // Ah, Al, Bh, Bl
#define DSMEM (2 * STAGEB)       // 147456 B double-buffered

// Scratch (device globals; no allocation allowed). 256B aligned for 16B vec ops.
__device__ __align__(256) float g_S[NSEG * NN];
__device__ __align__(256) float g_P[NN * NN];           // P[c][d] = T[d,c]
__device__ __align__(256) __nv_bfloat16 g_Mh[NN * NN];  // M[a][c] hi, row-major
__device__ __align__(256) __nv_bfloat16 g_Ml[NN * NN];  // M[a][c] lo
__device__ __align__(256) __nv_bfloat16 g_xh[(size_t)BB * NN];
__device__ __align__(256) __nv_bfloat16 g_xl[(size_t)BB * NN];

// ---------------------------------------------------------------------------
// helpers
// ---------------------------------------------------------------------------
__device__ __forceinline__ uint32_t cvta_smem(const void* p) {
    uint32_t a;
    asm("{ .reg .u64 t; cvta.to.shared.u64 t, %1; cvt.u32.u64 %0, t; }" : "=r"(a) : "l"(p));
    return a;
}
__device__ __forceinline__ void cpasync16(uint32_t s, const void* g) {
    asm volatile("cp.async.cg.shared.global [%0], [%1], 16;" :: "r"(s), "l"(g));
}
__device__ __forceinline__ void cp_commit() {
    asm volatile("cp.async.commit_group;" ::: "memory");
}
template <int N> __device__ __forceinline__ void cp_wait() {
    asm volatile("cp.async.wait_group %0;" :: "n"(N) : "memory");
}
__device__ __forceinline__ void ldm_x4(uint32_t* r, uint32_t addr) {
    asm volatile("ldmatrix.sync.aligned.m8n8.x4.shared.b16 {%0,%1,%2,%3}, [%4];"
                 : "=r"(r[0]), "=r"(r[1]), "=r"(r[2]), "=r"(r[3]) : "r"(addr));
}
__device__ __forceinline__ void mma16816(float* c, const uint32_t* a, const uint32_t* b) {
    asm volatile(
        "mma.sync.aligned.m16n8k16.row.col.f32.bf16.bf16.f32 "
        "{%0,%1,%2,%3}, {%4,%5,%6,%7}, {%8,%9}, {%0,%1,%2,%3};"
        : "+f"(c[0]), "+f"(c[1]), "+f"(c[2]), "+f"(c[3])
        : "r"(a[0]), "r"(a[1]), "r"(a[2]), "r"(a[3]), "r"(b[0]), "r"(b[1]));
}

// ---------------------------------------------------------------------------
// Kernel 1a: segment partial sums.  S[seg][d] = sum_{c in seg} V[d,c]
// ---------------------------------------------------------------------------
__global__ void scan_pass1(const float* __restrict__ G, const float* __restrict__ H) {
    const int d = blockIdx.x * blockDim.x + threadIdx.x;
    const int seg = blockIdx.y;
    const int cbeg = seg * SEGLEN;
    float acc = 0.0f;
#pragma unroll 4
    for (int c = cbeg; c < cbeg + SEGLEN; ++c) {
        const int s = (d + c) & (NN - 1);
        float v = G[s] * H[c];
        v = fmaf(G[NN + s], H[NN + c], v);
        v = fmaf(G[2 * NN + s], H[2 * NN + c], v);
        v = fmaf(G[3 * NN + s], H[3 * NN + c], v);
        acc += v;
    }
    g_S[seg * NN + d] = acc;
}

// ---------------------------------------------------------------------------
// Kernel 1b: per-segment prefix with segment offset.  P[c][d] = T[d,c]
// ---------------------------------------------------------------------------
__global__ void scan_pass2(const float* __restrict__ G, const float* __restrict__ H) {
    const int d = blockIdx.x * blockDim.x + threadIdx.x;
    const int seg = blockIdx.y;
    float acc = 0.0f;
    for (int s2 = 0; s2 < seg; ++s2) acc += g_S[s2 * NN + d];
    const int cbeg = seg * SEGLEN;
#pragma unroll 4
    for (int c = cbeg; c < cbeg + SEGLEN; ++c) {
        const int s = (d + c) & (NN - 1);
        float v = G[s] * H[c];
        v = fmaf(G[NN + s], H[NN + c], v);
        v = fmaf(G[2 * NN + s], H[2 * NN + c], v);
        v = fmaf(G[3 * NN + s], H[3 * NN + c], v);
        acc += v;
        g_P[c * NN + d] = acc;
    }
}

// ---------------------------------------------------------------------------
// Kernel 2: M[a][c] = 2*P[c][d] - P[NN-1][d], d=(a-c)%n; transpose + bf16 split
// ---------------------------------------------------------------------------
__global__ void build_m_kernel() {
    __shared__ float tile[32][33];
    const int a0 = blockIdx.x * 32;
    const int c0 = blockIdx.y * 32;
    const int tx = threadIdx.x;
#pragma unroll
    for (int yy = threadIdx.y; yy < 32; yy += 8) {
        const int c = c0 + yy;
        const int d = (a0 + tx - c) & (NN - 1);
        tile[yy][tx] = 2.0f * g_P[c * NN + d] - g_P[(NN - 1) * NN + d];
    }
    __syncthreads();
#pragma unroll
    for (int yy = threadIdx.y; yy < 32; yy += 8) {
        const int a = a0 + yy;
        const int c = c0 + tx;
        const float m = tile[tx][yy];
        const __nv_bfloat16 h = __float2bfloat16(m);
        g_Mh[(size_t)a * NN + c] = h;
        g_Ml[(size_t)a * NN + c] = __float2bfloat16(m - __bfloat162float(h));
    }
}

// ---------------------------------------------------------------------------
// Kernel 3: split x into bf16 hi/lo
// ---------------------------------------------------------------------------
__global__ void convert_x_kernel(const float* __restrict__ x) {
    const size_t i = ((size_t)blockIdx.x * blockDim.x + threadIdx.x) * 4;
    const float4 v = *reinterpret_cast<const float4*>(x + i);
    __nv_bfloat16 h0 = __float2bfloat16(v.x);
    __nv_bfloat16 h1 = __float2bfloat16(v.y);
    __nv_bfloat16 h2 = __float2bfloat16(v.z);
    __nv_bfloat16 h3 = __float2bfloat16(v.w);
    __nv_bfloat162* dh = reinterpret_cast<__nv_bfloat162*>(&g_xh[i]);
    dh[0] = __nv_bfloat162(h0, h1);
    dh[1] = __nv_bfloat162(h2, h3);
    __nv_bfloat162* dl = reinterpret_cast<__nv_bfloat162*>(&g_xl[i]);
    dl[0] = __nv_bfloat162(__float2bfloat16(v.x - __bfloat162float(h0)),
                           __float2bfloat16(v.y - __bfloat162float(h1)));
    dl[1] = __nv_bfloat162(__float2bfloat16(v.z - __bfloat162float(h2)),
                           __float2bfloat16(v.w - __bfloat162float(h3)));
}

// ---------------------------------------------------------------------------
// Kernel 4: HMMA GEMM.  C[b][a] = sum_c x[b][c] * M[a][c]
// A = x hi/lo (row-major, K contiguous), B = M hi/lo (N-major rows, K contiguous)
// 3-product bf16 split into fp32 accumulators. mma.sync m16n8k16 row.col.
// ---------------------------------------------------------------------------
__global__ __launch_bounds__(256, 1)
void gemm_mma(float* __restrict__ C) {
    extern __shared__ char dsm[];
    const uint32_t sb = cvta_smem(dsm);

    const int tid = threadIdx.x;
    const int wid = tid >> 5;
    const int lid = tid & 31;
    const int m0 = blockIdx.y * BM;   // batch rows
    const int n0 = blockIdx.x * BN;   // output cols = M rows

    const int warp_m = (wid & 1) * 64;   // 2 warps in M
    const int warp_n = (wid >> 1) * 32;  // 4 warps in N

    const char* gbase[4] = {
        (const char*)g_xh + (size_t)m0 * (NN * 2),
        (const char*)g_xl + (size_t)m0 * (NN * 2),
        (const char*)g_Mh + (size_t)n0 * (NN * 2),
        (const char*)g_Ml + (size_t)n0 * (NN * 2)};

    // gmem->smem loader: 2 threads per row, 64B each
    const int ld_row = tid >> 1;
    const int ld_half = (tid & 1) * 64;

    auto load_chunk = [&](int ch) {
        const uint32_t st = sb + (uint32_t)(ch & 1) * STAGEB;
#pragma unroll
        for (int o = 0; o < 4; ++o) {
            const char* g = gbase[o] + (size_t)ld_row * (NN * 2) + ch * (BKK * 2) + ld_half;
            const uint32_t s = st + o * TILEB + ld_row * ROWB + ld_half;
#pragma unroll
            for (int i = 0; i < 4; ++i) cpasync16(s + i * 16, g + i * 16);
        }
        cp_commit();
    };

    float acc[4][4][4];
#pragma unroll
    for (int i = 0; i < 4; ++i)
#pragma unroll
        for (int j = 0; j < 4; ++j)
#pragma unroll
            for (int q = 0; q < 4; ++q) acc[i][j][q] = 0.0f;

    // ldmatrix per-lane coords
    const int a_row = warp_m + (lid & 15);
    const int a_kadd = (lid >> 4) * 8;
    const int b_n = warp_n + ((lid >> 4) << 3) + (lid & 7);
    const int b_kadd = ((lid >> 3) & 1) * 8;

    load_chunk(0);
    load_chunk(1);

    for (int ch = 0; ch < NCH; ++ch) {
        if (ch + 1 < NCH) cp_wait<1>(); else cp_wait<0>();
        __syncthreads();

        const uint32_t st = sb + (uint32_t)(ch & 1) * STAGEB;
        const uint32_t tAh = st;
        const uint32_t tAl = st + TILEB;
        const uint32_t tBh = st + 2 * TILEB;
        const uint32_t tBl = st + 3 * TILEB;

#pragma unroll
        for (int ks = 0; ks < 4; ++ks) {
            const int kk = ks * 16;
            uint32_t ah[4][4], al[4][4], bh[2][4], bl[2][4];
#pragma unroll
            for (int i = 0; i < 4; ++i) {
                const uint32_t off = (uint32_t)(a_row + i * 16) * ROWB + (kk + a_kadd) * 2;
                ldm_x4(ah[i], tAh + off);
                ldm_x4(al[i], tAl + off);
            }
#pragma unroll
            for (int jj = 0; jj < 2; ++jj) {
                const uint32_t off = (uint32_t)(b_n + jj * 16) * ROWB + (kk + b_kadd) * 2;
                ldm_x4(bh[jj], tBh + off);
                ldm_x4(bl[jj], tBl + off);
            }
#pragma unroll
            for (int i = 0; i < 4; ++i)
#pragma unroll
                for (int j = 0; j < 4; ++j) {
                    const uint32_t* bhp = &bh[j >> 1][(j & 1) * 2];
                    const uint32_t* blp = &bl[j >> 1][(j & 1) * 2];
                    mma16816(acc[i][j], ah[i], bhp);
                    mma16816(acc[i][j], ah[i], blp);
                    mma16816(acc[i][j], al[i], bhp);
                }
        }
        __syncthreads();
        if (ch + 2 < NCH) load_chunk(ch + 2);
    }

    // epilogue: c frag (m16n8): c0,c1 @ (row=l>>2, col=(l&3)*2), c2,c3 @ row+8
    const int er = lid >> 2;
    const int ec = (lid & 3) * 2;
#pragma unroll
    for (int i = 0; i < 4; ++i) {
        const int row = m0 + warp_m + i * 16 + er;
#pragma unroll
        for (int j = 0; j < 4; ++j) {
            const int col = n0 + warp_n + j * 8 + ec;
            float2* p0 = reinterpret_cast<float2*>(C + (size_t)row * NN + col);
            float2* p1 = reinterpret_cast<float2*>(C + (size_t)(row + 8) * NN + col);
            *p0 = make_float2(acc[i][j][0], acc[i][j][1]);
            *p1 = make_float2(acc[i][j][2], acc[i][j][3]);
        }
    }
}

// ---------------------------------------------------------------------------
extern "C" void kernel_launch(void* const* d_in, const int* in_sizes, int n_in,
                              void* d_out, int out_size) {
    const float* x = (const float*)d_in[0];  // (BB, NN)
    const float* G = (const float*)d_in[1];  // (RR, NN)
    const float* H = (const float*)d_in[2];  // (RR, NN)
    float* out = (float*)d_out;              // (BB, NN)

    cudaFuncSetAttribute(gemm_mma, cudaFuncAttributeMaxDynamicSharedMemorySize, DSMEM);

    convert_x_kernel<<<(BB * NN / 4) / 256, 256>>>(x);
    scan_pass1<<<dim3(NN / 256, NSEG), 256>>>(G, H);
    scan_pass2<<<dim3(NN / 256, NSEG), 256>>>(G, H);
    build_m_kernel<<<dim3(NN / 32, NN / 32), dim3(32, 8)>>>();
    gemm_mma<<<dim3(NN / BN, BB / BM), 256, DSMEM>>>(out);
}

// round 5
// speedup vs baseline: 4.6924x; 2.2147x over previous
#include <cuda_runtime.h>
#include <cuda_fp16.h>
#include <cstdint>

// Problem constants
#define NN 2048
#define RR 4
#define BB 4096
#define NSEG 16
#define SEGLEN (NN / NSEG)

// GEMM tiling
#define BM 128
#define BN 128
#define BKK 64                   // K elems per chunk (fp16)
#define NCH (NN / BKK)           // 32 chunks
#define SSTRIDE 72               // smem row stride in fp16 (64 data + 8 pad) = 144B
#define ROWB (SSTRIDE * 2)       // 144 bytes, 16B-aligned, conflict-free ldmatrix
#define TILEB (128 * ROWB)       // 18432 B per operand tile
#define STAGEB (2 * TILEB)       // A, B
#define NSTAGE 3
#define DSMEM (NSTAGE * STAGEB)  // 110592 B

// Scratch (device globals; no allocation allowed)
__device__ __align__(256) float g_S[NSEG * NN];
__device__ __align__(256) float g_P[NN * NN];        // P[c][d] = T[d,c]
__device__ __align__(256) __half g_Mf[NN * NN];      // M[a][c], row-major (K contiguous)
__device__ __align__(256) __half g_xf[(size_t)BB * NN];

// ---------------------------------------------------------------------------
// helpers
// ---------------------------------------------------------------------------
__device__ __forceinline__ uint32_t cvta_smem(const void* p) {
    uint32_t a;
    asm("{ .reg .u64 t; cvta.to.shared.u64 t, %1; cvt.u32.u64 %0, t; }" : "=r"(a) : "l"(p));
    return a;
}
__device__ __forceinline__ void cpasync16(uint32_t s, const void* g) {
    asm volatile("cp.async.cg.shared.global [%0], [%1], 16;" :: "r"(s), "l"(g));
}
__device__ __forceinline__ void cp_commit() {
    asm volatile("cp.async.commit_group;" ::: "memory");
}
template <int N> __device__ __forceinline__ void cp_wait() {
    asm volatile("cp.async.wait_group %0;" :: "n"(N) : "memory");
}
__device__ __forceinline__ void ldm_x4(uint32_t* r, uint32_t addr) {
    asm volatile("ldmatrix.sync.aligned.m8n8.x4.shared.b16 {%0,%1,%2,%3}, [%4];"
                 : "=r"(r[0]), "=r"(r[1]), "=r"(r[2]), "=r"(r[3]) : "r"(addr));
}
__device__ __forceinline__ void mma16816(float* c, const uint32_t* a, const uint32_t* b) {
    asm volatile(
        "mma.sync.aligned.m16n8k16.row.col.f32.f16.f16.f32 "
        "{%0,%1,%2,%3}, {%4,%5,%6,%7}, {%8,%9}, {%0,%1,%2,%3};"
        : "+f"(c[0]), "+f"(c[1]), "+f"(c[2]), "+f"(c[3])
        : "r"(a[0]), "r"(a[1]), "r"(a[2]), "r"(a[3]), "r"(b[0]), "r"(b[1]));
}

// ---------------------------------------------------------------------------
// Kernel 1a: segment partial sums.  S[seg][d] = sum_{c in seg} V[d,c]
// ---------------------------------------------------------------------------
__global__ void scan_pass1(const float* __restrict__ G, const float* __restrict__ H) {
    const int d = blockIdx.x * blockDim.x + threadIdx.x;
    const int seg = blockIdx.y;
    const int cbeg = seg * SEGLEN;
    float acc = 0.0f;
#pragma unroll 4
    for (int c = cbeg; c < cbeg + SEGLEN; ++c) {
        const int s = (d + c) & (NN - 1);
        float v = G[s] * H[c];
        v = fmaf(G[NN + s], H[NN + c], v);
        v = fmaf(G[2 * NN + s], H[2 * NN + c], v);
        v = fmaf(G[3 * NN + s], H[3 * NN + c], v);
        acc += v;
    }
    g_S[seg * NN + d] = acc;
}

// ---------------------------------------------------------------------------
// Kernel 1b: per-segment prefix with segment offset.  P[c][d] = T[d,c]
// ---------------------------------------------------------------------------
__global__ void scan_pass2(const float* __restrict__ G, const float* __restrict__ H) {
    const int d = blockIdx.x * blockDim.x + threadIdx.x;
    const int seg = blockIdx.y;
    float acc = 0.0f;
    for (int s2 = 0; s2 < seg; ++s2) acc += g_S[s2 * NN + d];
    const int cbeg = seg * SEGLEN;
#pragma unroll 4
    for (int c = cbeg; c < cbeg + SEGLEN; ++c) {
        const int s = (d + c) & (NN - 1);
        float v = G[s] * H[c];
        v = fmaf(G[NN + s], H[NN + c], v);
        v = fmaf(G[2 * NN + s], H[2 * NN + c], v);
        v = fmaf(G[3 * NN + s], H[3 * NN + c], v);
        acc += v;
        g_P[c * NN + d] = acc;
    }
}

// ---------------------------------------------------------------------------
// Kernel 2: M[a][c] = 2*P[c][d] - P[NN-1][d], d=(a-c)%n; transpose + fp16
// ---------------------------------------------------------------------------
__global__ void build_m_kernel() {
    __shared__ float tile[32][33];
    const int a0 = blockIdx.x * 32;
    const int c0 = blockIdx.y * 32;
    const int tx = threadIdx.x;
#pragma unroll
    for (int yy = threadIdx.y; yy < 32; yy += 8) {
        const int c = c0 + yy;
        const int d = (a0 + tx - c) & (NN - 1);
        tile[yy][tx] = 2.0f * g_P[c * NN + d] - g_P[(NN - 1) * NN + d];
    }
    __syncthreads();
#pragma unroll
    for (int yy = threadIdx.y; yy < 32; yy += 8) {
        const int a = a0 + yy;
        const int c = c0 + tx;
        g_Mf[(size_t)a * NN + c] = __float2half(tile[tx][yy]);
    }
}

// ---------------------------------------------------------------------------
// Kernel 3: convert x to fp16
// ---------------------------------------------------------------------------
__global__ void convert_x_kernel(const float* __restrict__ x) {
    const size_t i = ((size_t)blockIdx.x * blockDim.x + threadIdx.x) * 4;
    const float4 v = *reinterpret_cast<const float4*>(x + i);
    __half2* dh = reinterpret_cast<__half2*>(&g_xf[i]);
    dh[0] = __half2(__float2half(v.x), __float2half(v.y));
    dh[1] = __half2(__float2half(v.z), __float2half(v.w));
}

// ---------------------------------------------------------------------------
// Kernel 4: fp16 HMMA GEMM.  C[b][a] = sum_c x[b][c] * M[a][c]
// A = x fp16 (row-major, K contiguous), B = M fp16 (N rows, K contiguous)
// 3-stage cp.async pipeline, 2 CTAs/SM, warp tile 64x32 (2M x 4N warps).
// ---------------------------------------------------------------------------
__global__ __launch_bounds__(256, 2)
void gemm_mma(float* __restrict__ C) {
    extern __shared__ char dsm[];
    const uint32_t sb = cvta_smem(dsm);

    const int tid = threadIdx.x;
    const int wid = tid >> 5;
    const int lid = tid & 31;
    const int m0 = blockIdx.y * BM;
    const int n0 = blockIdx.x * BN;

    const int warp_m = (wid & 1) * 64;
    const int warp_n = (wid >> 1) * 32;

    const char* gA = (const char*)g_xf + (size_t)m0 * (NN * 2);
    const char* gB = (const char*)g_Mf + (size_t)n0 * (NN * 2);

    // loader: 2 threads per row, 64B halves
    const int ld_row = tid >> 1;
    const int ld_half = (tid & 1) * 64;

    auto load_chunk = [&](int ch) {
        const uint32_t st = sb + (uint32_t)(ch % NSTAGE) * STAGEB;
        {
            const char* g = gA + (size_t)ld_row * (NN * 2) + ch * (BKK * 2) + ld_half;
            const uint32_t s = st + ld_row * ROWB + ld_half;
#pragma unroll
            for (int i = 0; i < 4; ++i) cpasync16(s + i * 16, g + i * 16);
        }
        {
            const char* g = gB + (size_t)ld_row * (NN * 2) + ch * (BKK * 2) + ld_half;
            const uint32_t s = st + TILEB + ld_row * ROWB + ld_half;
#pragma unroll
            for (int i = 0; i < 4; ++i) cpasync16(s + i * 16, g + i * 16);
        }
    };

    float acc[4][4][4];
#pragma unroll
    for (int i = 0; i < 4; ++i)
#pragma unroll
        for (int j = 0; j < 4; ++j)
#pragma unroll
            for (int q = 0; q < 4; ++q) acc[i][j][q] = 0.0f;

    const int a_row = warp_m + (lid & 15);
    const int a_kadd = (lid >> 4) * 8;
    const int b_n = warp_n + ((lid >> 4) << 3) + (lid & 7);
    const int b_kadd = ((lid >> 3) & 1) * 8;

    load_chunk(0); cp_commit();
    load_chunk(1); cp_commit();
    load_chunk(2); cp_commit();

    for (int ch = 0; ch < NCH; ++ch) {
        cp_wait<2>();
        __syncthreads();

        const uint32_t st = sb + (uint32_t)(ch % NSTAGE) * STAGEB;
        const uint32_t tA = st;
        const uint32_t tB = st + TILEB;

#pragma unroll
        for (int ks = 0; ks < 4; ++ks) {
            const int kk = ks * 16;
            uint32_t af[4][4], bf[2][4];
#pragma unroll
            for (int i = 0; i < 4; ++i) {
                const uint32_t off = (uint32_t)(a_row + i * 16) * ROWB + (kk + a_kadd) * 2;
                ldm_x4(af[i], tA + off);
            }
#pragma unroll
            for (int jj = 0; jj < 2; ++jj) {
                const uint32_t off = (uint32_t)(b_n + jj * 16) * ROWB + (kk + b_kadd) * 2;
                ldm_x4(bf[jj], tB + off);
            }
#pragma unroll
            for (int i = 0; i < 4; ++i)
#pragma unroll
                for (int j = 0; j < 4; ++j)
                    mma16816(acc[i][j], af[i], &bf[j >> 1][(j & 1) * 2]);
        }
        __syncthreads();
        if (ch + NSTAGE < NCH) load_chunk(ch + NSTAGE);
        cp_commit();
    }

    // epilogue
    const int er = lid >> 2;
    const int ec = (lid & 3) * 2;
#pragma unroll
    for (int i = 0; i < 4; ++i) {
        const int row = m0 + warp_m + i * 16 + er;
#pragma unroll
        for (int j = 0; j < 4; ++j) {
            const int col = n0 + warp_n + j * 8 + ec;
            float2* p0 = reinterpret_cast<float2*>(C + (size_t)row * NN + col);
            float2* p1 = reinterpret_cast<float2*>(C + (size_t)(row + 8) * NN + col);
            *p0 = make_float2(acc[i][j][0], acc[i][j][1]);
            *p1 = make_float2(acc[i][j][2], acc[i][j][3]);
        }
    }
}

// ---------------------------------------------------------------------------
extern "C" void kernel_launch(void* const* d_in, const int* in_sizes, int n_in,
                              void* d_out, int out_size) {
    const float* x = (const float*)d_in[0];  // (BB, NN)
    const float* G = (const float*)d_in[1];  // (RR, NN)
    const float* H = (const float*)d_in[2];  // (RR, NN)
    float* out = (float*)d_out;              // (BB, NN)

    cudaFuncSetAttribute(gemm_mma, cudaFuncAttributeMaxDynamicSharedMemorySize, DSMEM);

    convert_x_kernel<<<(BB * NN / 4) / 256, 256>>>(x);
    scan_pass1<<<dim3(NN / 256, NSEG), 256>>>(G, H);
    scan_pass2<<<dim3(NN / 256, NSEG), 256>>>(G, H);
    build_m_kernel<<<dim3(NN / 32, NN / 32), dim3(32, 8)>>>();
    gemm_mma<<<dim3(NN / BN, BB / BM), 256, DSMEM>>>(out);
}

// round 6
// speedup vs baseline: 5.0950x; 1.0858x over previous
#include <cuda_runtime.h>
#include <cuda_fp16.h>
#include <cstdint>

// Problem constants
#define NN 2048
#define RR 4
#define BB 4096
#define NSEG 32
#define SEGLEN (NN / NSEG)

// GEMM tiling: CTA 128(M=batch) x 256(N=outputs), K-chunk 64, 8 warps @ 64x64
#define BM 128
#define BN 256
#define BKK 64
#define NCH (NN / BKK)           // 32 chunks
#define SSTRIDE 72               // smem row stride fp16 (64 data + 8 pad) = 144B
#define ROWB (SSTRIDE * 2)       // 144 B, conflict-free ldmatrix
#define ATILEB (BM * ROWB)       // 18432 B
#define BTILEB (BN * ROWB)       // 36864 B
#define STAGEB (ATILEB + BTILEB) // 55296 B... (wait: 18432+36864=55296)
#define NSTAGE 3
#define DSMEM (NSTAGE * STAGEB)  // 165888 B

// Scratch
__device__ __align__(256) float g_S[NSEG * NN];
__device__ __align__(256) float g_P[NN * NN];        // P[c][d] = T[d,c]
__device__ __align__(256) __half g_Mf[NN * NN];      // M[a][c], row-major
__device__ __align__(256) __half g_xf[(size_t)BB * NN];

// ---------------------------------------------------------------------------
__device__ __forceinline__ uint32_t cvta_smem(const void* p) {
    uint32_t a;
    asm("{ .reg .u64 t; cvta.to.shared.u64 t, %1; cvt.u32.u64 %0, t; }" : "=r"(a) : "l"(p));
    return a;
}
__device__ __forceinline__ void cpasync16(uint32_t s, const void* g) {
    asm volatile("cp.async.cg.shared.global [%0], [%1], 16;" :: "r"(s), "l"(g));
}
__device__ __forceinline__ void cp_commit() {
    asm volatile("cp.async.commit_group;" ::: "memory");
}
template <int N> __device__ __forceinline__ void cp_wait() {
    asm volatile("cp.async.wait_group %0;" :: "n"(N) : "memory");
}
__device__ __forceinline__ void ldm_x4(uint32_t* r, uint32_t addr) {
    asm volatile("ldmatrix.sync.aligned.m8n8.x4.shared.b16 {%0,%1,%2,%3}, [%4];"
                 : "=r"(r[0]), "=r"(r[1]), "=r"(r[2]), "=r"(r[3]) : "r"(addr));
}
__device__ __forceinline__ void mma16816(float* c, const uint32_t* a, const uint32_t* b) {
    asm volatile(
        "mma.sync.aligned.m16n8k16.row.col.f32.f16.f16.f32 "
        "{%0,%1,%2,%3}, {%4,%5,%6,%7}, {%8,%9}, {%0,%1,%2,%3};"
        : "+f"(c[0]), "+f"(c[1]), "+f"(c[2]), "+f"(c[3])
        : "r"(a[0]), "r"(a[1]), "r"(a[2]), "r"(a[3]), "r"(b[0]), "r"(b[1]));
}

// ---------------------------------------------------------------------------
// Kernel 1a: segment partial sums
// ---------------------------------------------------------------------------
__global__ void scan_pass1(const float* __restrict__ G, const float* __restrict__ H) {
    const int d = blockIdx.x * blockDim.x + threadIdx.x;
    const int seg = blockIdx.y;
    const int cbeg = seg * SEGLEN;
    float acc = 0.0f;
#pragma unroll 4
    for (int c = cbeg; c < cbeg + SEGLEN; ++c) {
        const int s = (d + c) & (NN - 1);
        float v = G[s] * H[c];
        v = fmaf(G[NN + s], H[NN + c], v);
        v = fmaf(G[2 * NN + s], H[2 * NN + c], v);
        v = fmaf(G[3 * NN + s], H[3 * NN + c], v);
        acc += v;
    }
    g_S[seg * NN + d] = acc;
}

// ---------------------------------------------------------------------------
// Kernel 1b: per-segment prefix with segment offset.  P[c][d] = T[d,c]
// ---------------------------------------------------------------------------
__global__ void scan_pass2(const float* __restrict__ G, const float* __restrict__ H) {
    const int d = blockIdx.x * blockDim.x + threadIdx.x;
    const int seg = blockIdx.y;
    float acc = 0.0f;
#pragma unroll
    for (int s2 = 0; s2 < NSEG; ++s2)
        if (s2 < seg) acc += g_S[s2 * NN + d];
    const int cbeg = seg * SEGLEN;
#pragma unroll 4
    for (int c = cbeg; c < cbeg + SEGLEN; ++c) {
        const int s = (d + c) & (NN - 1);
        float v = G[s] * H[c];
        v = fmaf(G[NN + s], H[NN + c], v);
        v = fmaf(G[2 * NN + s], H[2 * NN + c], v);
        v = fmaf(G[3 * NN + s], H[3 * NN + c], v);
        acc += v;
        g_P[c * NN + d] = acc;
    }
}

// ---------------------------------------------------------------------------
// Kernel 2: M[a][c] = 2*P[c][d] - P[NN-1][d], d=(a-c)%n; transpose + fp16
// ---------------------------------------------------------------------------
__global__ void build_m_kernel() {
    __shared__ float tile[32][33];
    const int a0 = blockIdx.x * 32;
    const int c0 = blockIdx.y * 32;
    const int tx = threadIdx.x;
#pragma unroll
    for (int yy = threadIdx.y; yy < 32; yy += 8) {
        const int c = c0 + yy;
        const int d = (a0 + tx - c) & (NN - 1);
        tile[yy][tx] = 2.0f * g_P[c * NN + d] - g_P[(NN - 1) * NN + d];
    }
    __syncthreads();
#pragma unroll
    for (int yy = threadIdx.y; yy < 32; yy += 8) {
        const int a = a0 + yy;
        const int c = c0 + tx;
        g_Mf[(size_t)a * NN + c] = __float2half(tile[tx][yy]);
    }
}

// ---------------------------------------------------------------------------
// Kernel 3: convert x to fp16
// ---------------------------------------------------------------------------
__global__ void convert_x_kernel(const float* __restrict__ x) {
    const size_t i = ((size_t)blockIdx.x * blockDim.x + threadIdx.x) * 4;
    const float4 v = *reinterpret_cast<const float4*>(x + i);
    __half2* dh = reinterpret_cast<__half2*>(&g_xf[i]);
    dh[0] = __half2(__float2half(v.x), __float2half(v.y));
    dh[1] = __half2(__float2half(v.z), __float2half(v.w));
}

// ---------------------------------------------------------------------------
// Kernel 4: fp16 HMMA GEMM.  C[b][a] = sum_c x[b][c] * M[a][c]
// CTA 128x256, warp tile 64x64 (2Mx4N warps), 3-stage cp.async, 1 sync/chunk.
// ---------------------------------------------------------------------------
__global__ __launch_bounds__(256, 1)
void gemm_mma(float* __restrict__ C) {
    extern __shared__ char dsm[];
    const uint32_t sb = cvta_smem(dsm);

    const int tid = threadIdx.x;
    const int wid = tid >> 5;
    const int lid = tid & 31;
    const int m0 = blockIdx.y * BM;
    const int n0 = blockIdx.x * BN;

    const int warp_m = (wid & 1) * 64;
    const int warp_n = (wid >> 1) * 64;

    const char* gA = (const char*)g_xf + (size_t)m0 * (NN * 2);
    const char* gB = (const char*)g_Mf + (size_t)n0 * (NN * 2);

    const int ld_row = tid >> 1;          // 0..127
    const int ld_half = (tid & 1) * 64;   // 0 or 64 bytes

    auto load_chunk = [&](int ch) {
        const uint32_t st = sb + (uint32_t)(ch % NSTAGE) * STAGEB;
        // A: 128 rows
        {
            const char* g = gA + (size_t)ld_row * (NN * 2) + ch * (BKK * 2) + ld_half;
            const uint32_t s = st + ld_row * ROWB + ld_half;
#pragma unroll
            for (int i = 0; i < 4; ++i) cpasync16(s + i * 16, g + i * 16);
        }
        // B: 256 rows (two passes of 128)
#pragma unroll
        for (int r2 = 0; r2 < 2; ++r2) {
            const int row = ld_row + r2 * 128;
            const char* g = gB + (size_t)row * (NN * 2) + ch * (BKK * 2) + ld_half;
            const uint32_t s = st + ATILEB + row * ROWB + ld_half;
#pragma unroll
            for (int i = 0; i < 4; ++i) cpasync16(s + i * 16, g + i * 16);
        }
        cp_commit();
    };

    float acc[4][8][4];
#pragma unroll
    for (int i = 0; i < 4; ++i)
#pragma unroll
        for (int j = 0; j < 8; ++j)
#pragma unroll
            for (int q = 0; q < 4; ++q) acc[i][j][q] = 0.0f;

    const int a_row = warp_m + (lid & 15);
    const int a_kadd = (lid >> 4) * 8;
    const int b_n = warp_n + ((lid >> 4) << 3) + (lid & 7);
    const int b_kadd = ((lid >> 3) & 1) * 8;

    load_chunk(0);
    load_chunk(1);

    for (int ch = 0; ch < NCH; ++ch) {
        cp_wait<1>();
        __syncthreads();
        if (ch + 2 < NCH) load_chunk(ch + 2);

        const uint32_t st = sb + (uint32_t)(ch % NSTAGE) * STAGEB;
        const uint32_t tA = st;
        const uint32_t tB = st + ATILEB;

#pragma unroll
        for (int ks = 0; ks < 4; ++ks) {
            const int kk = ks * 16;
            uint32_t af[4][4], bf[4][4];
#pragma unroll
            for (int i = 0; i < 4; ++i) {
                const uint32_t off = (uint32_t)(a_row + i * 16) * ROWB + (kk + a_kadd) * 2;
                ldm_x4(af[i], tA + off);
            }
#pragma unroll
            for (int jj = 0; jj < 4; ++jj) {
                const uint32_t off = (uint32_t)(b_n + jj * 16) * ROWB + (kk + b_kadd) * 2;
                ldm_x4(bf[jj], tB + off);
            }
#pragma unroll
            for (int i = 0; i < 4; ++i)
#pragma unroll
                for (int j = 0; j < 8; ++j)
                    mma16816(acc[i][j], af[i], &bf[j >> 1][(j & 1) * 2]);
        }
    }

    // epilogue
    const int er = lid >> 2;
    const int ec = (lid & 3) * 2;
#pragma unroll
    for (int i = 0; i < 4; ++i) {
        const int row = m0 + warp_m + i * 16 + er;
#pragma unroll
        for (int j = 0; j < 8; ++j) {
            const int col = n0 + warp_n + j * 8 + ec;
            float2* p0 = reinterpret_cast<float2*>(C + (size_t)row * NN + col);
            float2* p1 = reinterpret_cast<float2*>(C + (size_t)(row + 8) * NN + col);
            *p0 = make_float2(acc[i][j][0], acc[i][j][1]);
            *p1 = make_float2(acc[i][j][2], acc[i][j][3]);
        }
    }
}

// ---------------------------------------------------------------------------
extern "C" void kernel_launch(void* const* d_in, const int* in_sizes, int n_in,
                              void* d_out, int out_size) {
    const float* x = (const float*)d_in[0];  // (BB, NN)
    const float* G = (const float*)d_in[1];  // (RR, NN)
    const float* H = (const float*)d_in[2];  // (RR, NN)
    float* out = (float*)d_out;              // (BB, NN)

    cudaFuncSetAttribute(gemm_mma, cudaFuncAttributeMaxDynamicSharedMemorySize, DSMEM);

    convert_x_kernel<<<(BB * NN / 4) / 256, 256>>>(x);
    scan_pass1<<<dim3(NN / 256, NSEG), 256>>>(G, H);
    scan_pass2<<<dim3(NN / 256, NSEG), 256>>>(G, H);
    build_m_kernel<<<dim3(NN / 32, NN / 32), dim3(32, 8)>>>();
    gemm_mma<<<dim3(NN / BN, BB / BM), 256, DSMEM>>>(out);
}

// round 8
// speedup vs baseline: 5.2781x; 1.0359x over previous
#include <cuda_runtime.h>
#include <cuda_fp16.h>
#include <cstdint>

// Problem constants
#define NN 2048
#define RR 4
#define BB 4096
#define NSEG 32
#define SEGLEN (NN / NSEG)

// GEMM tiling: CTA 256(M=batch) x 128(N=outputs), 16 warps @ 64x32 (4M x 4N)
#define BM 256
#define BN 128
#define BKK 64
#define NCH (NN / BKK)           // 32 chunks
#define SSTRIDE 72               // smem row stride fp16 (64 data + 8 pad) = 144B
#define ROWB (SSTRIDE * 2)       // 144 B, conflict-free ldmatrix
#define ATILEB (BM * ROWB)       // 36864 B
#define BTILEB (BN * ROWB)       // 18432 B
#define STAGEB (ATILEB + BTILEB) // 55296 B
#define NSTAGE 3
#define DSMEM (NSTAGE * STAGEB)  // 165888 B

// convert/scan fusion split
#define CONV_BLOCKS ((BB * NN / 4) / 256)   // 8192
#define SCAN_BLOCKS (NN / 256)              // 8 per segment

// Scratch
__device__ __align__(256) float g_S[NSEG * NN];
__device__ __align__(256) float g_P[NN * NN];        // P[c][d] = T[d,c]
__device__ __align__(256) __half g_Mf[NN * NN];      // M[a][c], row-major
__device__ __align__(256) __half g_xf[(size_t)BB * NN];

// ---------------------------------------------------------------------------
__device__ __forceinline__ uint32_t cvta_smem(const void* p) {
    uint32_t a;
    asm("{ .reg .u64 t; cvta.to.shared.u64 t, %1; cvt.u32.u64 %0, t; }" : "=r"(a) : "l"(p));
    return a;
}
__device__ __forceinline__ void cpasync16(uint32_t s, const void* g) {
    asm volatile("cp.async.cg.shared.global [%0], [%1], 16;" :: "r"(s), "l"(g));
}
__device__ __forceinline__ void cp_commit() {
    asm volatile("cp.async.commit_group;" ::: "memory");
}
template <int N> __device__ __forceinline__ void cp_wait() {
    asm volatile("cp.async.wait_group %0;" :: "n"(N) : "memory");
}
__device__ __forceinline__ void ldm_x4(uint32_t* r, uint32_t addr) {
    asm volatile("ldmatrix.sync.aligned.m8n8.x4.shared.b16 {%0,%1,%2,%3}, [%4];"
                 : "=r"(r[0]), "=r"(r[1]), "=r"(r[2]), "=r"(r[3]) : "r"(addr));
}
__device__ __forceinline__ void mma16816(float* c, const uint32_t* a, const uint32_t* b) {
    asm volatile(
        "mma.sync.aligned.m16n8k16.row.col.f32.f16.f16.f32 "
        "{%0,%1,%2,%3}, {%4,%5,%6,%7}, {%8,%9}, {%0,%1,%2,%3};"
        : "+f"(c[0]), "+f"(c[1]), "+f"(c[2]), "+f"(c[3])
        : "r"(a[0]), "r"(a[1]), "r"(a[2]), "r"(a[3]), "r"(b[0]), "r"(b[1]));
}

// ---------------------------------------------------------------------------
// Kernel 1 (fused): convert x to fp16 + scan pass 1
// ---------------------------------------------------------------------------
__global__ void fused_conv_scan1(const float* __restrict__ x,
                                 const float* __restrict__ G,
                                 const float* __restrict__ H) {
    if (blockIdx.x < CONV_BLOCKS) {
        const size_t i = ((size_t)blockIdx.x * blockDim.x + threadIdx.x) * 4;
        const float4 v = *reinterpret_cast<const float4*>(x + i);
        __half2* dh = reinterpret_cast<__half2*>(&g_xf[i]);
        dh[0] = __half2(__float2half(v.x), __float2half(v.y));
        dh[1] = __half2(__float2half(v.z), __float2half(v.w));
    } else {
        const int bid = blockIdx.x - CONV_BLOCKS;
        const int seg = bid / SCAN_BLOCKS;
        const int d = (bid % SCAN_BLOCKS) * blockDim.x + threadIdx.x;
        const int cbeg = seg * SEGLEN;
        float acc = 0.0f;
#pragma unroll 4
        for (int c = cbeg; c < cbeg + SEGLEN; ++c) {
            const int s = (d + c) & (NN - 1);
            float v = G[s] * H[c];
            v = fmaf(G[NN + s], H[NN + c], v);
            v = fmaf(G[2 * NN + s], H[2 * NN + c], v);
            v = fmaf(G[3 * NN + s], H[3 * NN + c], v);
            acc += v;
        }
        g_S[seg * NN + d] = acc;
    }
}

// ---------------------------------------------------------------------------
// Kernel 2: per-segment prefix with segment offset.  P[c][d] = T[d,c]
// ---------------------------------------------------------------------------
__global__ void scan_pass2(const float* __restrict__ G, const float* __restrict__ H) {
    const int d = blockIdx.x * blockDim.x + threadIdx.x;
    const int seg = blockIdx.y;
    float acc = 0.0f;
#pragma unroll
    for (int s2 = 0; s2 < NSEG; ++s2)
        if (s2 < seg) acc += g_S[s2 * NN + d];
    const int cbeg = seg * SEGLEN;
#pragma unroll 4
    for (int c = cbeg; c < cbeg + SEGLEN; ++c) {
        const int s = (d + c) & (NN - 1);
        float v = G[s] * H[c];
        v = fmaf(G[NN + s], H[NN + c], v);
        v = fmaf(G[2 * NN + s], H[2 * NN + c], v);
        v = fmaf(G[3 * NN + s], H[3 * NN + c], v);
        acc += v;
        g_P[c * NN + d] = acc;
    }
}

// ---------------------------------------------------------------------------
// Kernel 3: M[a][c] = 2*P[c][d] - P[NN-1][d], d=(a-c)%n; transpose + fp16
// ---------------------------------------------------------------------------
__global__ void build_m_kernel() {
    __shared__ float tile[32][33];
    const int a0 = blockIdx.x * 32;
    const int c0 = blockIdx.y * 32;
    const int tx = threadIdx.x;
#pragma unroll
    for (int yy = threadIdx.y; yy < 32; yy += 8) {
        const int c = c0 + yy;
        const int d = (a0 + tx - c) & (NN - 1);
        tile[yy][tx] = 2.0f * g_P[c * NN + d] - g_P[(NN - 1) * NN + d];
    }
    __syncthreads();
#pragma unroll
    for (int yy = threadIdx.y; yy < 32; yy += 8) {
        const int a = a0 + yy;
        const int c = c0 + tx;
        g_Mf[(size_t)a * NN + c] = __float2half(tile[tx][yy]);
    }
}

// ---------------------------------------------------------------------------
// Kernel 4: fp16 HMMA GEMM.  C[b][a] = sum_c x[b][c] * M[a][c]
// CTA 256x128, 512 threads, 16 warps @ 64x32 (4M x 4N), 3-stage cp.async.
// ---------------------------------------------------------------------------
__global__ __launch_bounds__(512, 1)
void gemm_mma(float* __restrict__ C) {
    extern __shared__ char dsm[];
    const uint32_t sb = cvta_smem(dsm);

    const int tid = threadIdx.x;
    const int wid = tid >> 5;
    const int lid = tid & 31;
    const int m0 = blockIdx.y * BM;
    const int n0 = blockIdx.x * BN;

    const int warp_m = (wid & 3) * 64;   // 4 warps in M -> 256
    const int warp_n = (wid >> 2) * 32;  // 4 warps in N -> 128

    const char* gA = (const char*)g_xf + (size_t)m0 * (NN * 2);
    const char* gB = (const char*)g_Mf + (size_t)n0 * (NN * 2);

    // A loader: 2 threads/row, 64B halves (256 rows)
    const int lda_row = tid >> 1;
    const int lda_half = (tid & 1) * 64;
    // B loader: 4 threads/row, 32B quarters (128 rows)
    const int ldb_row = tid >> 2;
    const int ldb_q = (tid & 3) * 32;

    auto load_chunk = [&](int ch) {
        const uint32_t st = sb + (uint32_t)(ch % NSTAGE) * STAGEB;
        {
            const char* g = gA + (size_t)lda_row * (NN * 2) + ch * (BKK * 2) + lda_half;
            const uint32_t s = st + lda_row * ROWB + lda_half;
#pragma unroll
            for (int i = 0; i < 4; ++i) cpasync16(s + i * 16, g + i * 16);
        }
        {
            const char* g = gB + (size_t)ldb_row * (NN * 2) + ch * (BKK * 2) + ldb_q;
            const uint32_t s = st + ATILEB + ldb_row * ROWB + ldb_q;
#pragma unroll
            for (int i = 0; i < 2; ++i) cpasync16(s + i * 16, g + i * 16);
        }
        cp_commit();
    };

    float acc[4][4][4];
#pragma unroll
    for (int i = 0; i < 4; ++i)
#pragma unroll
        for (int j = 0; j < 4; ++j)
#pragma unroll
            for (int q = 0; q < 4; ++q) acc[i][j][q] = 0.0f;

    const int a_row = warp_m + (lid & 15);
    const int a_kadd = (lid >> 4) * 8;
    const int b_n = warp_n + ((lid >> 4) << 3) + (lid & 7);
    const int b_kadd = ((lid >> 3) & 1) * 8;

    load_chunk(0);
    load_chunk(1);

    for (int ch = 0; ch < NCH; ++ch) {
        cp_wait<1>();
        __syncthreads();
        if (ch + 2 < NCH) load_chunk(ch + 2);

        const uint32_t st = sb + (uint32_t)(ch % NSTAGE) * STAGEB;
        const uint32_t tA = st;
        const uint32_t tB = st + ATILEB;

#pragma unroll
        for (int ks = 0; ks < 4; ++ks) {
            const int kk = ks * 16;
            uint32_t af[4][4], bf[2][4];
#pragma unroll
            for (int i = 0; i < 4; ++i) {
                const uint32_t off = (uint32_t)(a_row + i * 16) * ROWB + (kk + a_kadd) * 2;
                ldm_x4(af[i], tA + off);
            }
#pragma unroll
            for (int jj = 0; jj < 2; ++jj) {
                const uint32_t off = (uint32_t)(b_n + jj * 16) * ROWB + (kk + b_kadd) * 2;
                ldm_x4(bf[jj], tB + off);
            }
#pragma unroll
            for (int i = 0; i < 4; ++i)
#pragma unroll
                for (int j = 0; j < 4; ++j)
                    mma16816(acc[i][j], af[i], &bf[j >> 1][(j & 1) * 2]);
        }
    }

    // epilogue
    const int er = lid >> 2;
    const int ec = (lid & 3) * 2;
#pragma unroll
    for (int i = 0; i < 4; ++i) {
        const int row = m0 + warp_m + i * 16 + er;
#pragma unroll
        for (int j = 0; j < 4; ++j) {
            const int col = n0 + warp_n + j * 8 + ec;
            float2* p0 = reinterpret_cast<float2*>(C + (size_t)row * NN + col);
            float2* p1 = reinterpret_cast<float2*>(C + (size_t)(row + 8) * NN + col);
            *p0 = make_float2(acc[i][j][0], acc[i][j][1]);
            *p1 = make_float2(acc[i][j][2], acc[i][j][3]);
        }
    }
}

// ---------------------------------------------------------------------------
extern "C" void kernel_launch(void* const* d_in, const int* in_sizes, int n_in,
                              void* d_out, int out_size) {
    const float* x = (const float*)d_in[0];  // (BB, NN)
    const float* G = (const float*)d_in[1];  // (RR, NN)
    const float* H = (const float*)d_in[2];  // (RR, NN)
    float* out = (float*)d_out;              // (BB, NN)

    cudaFuncSetAttribute(gemm_mma, cudaFuncAttributeMaxDynamicSharedMemorySize, DSMEM);

    fused_conv_scan1<<<CONV_BLOCKS + NSEG * SCAN_BLOCKS, 256>>>(x, G, H);
    scan_pass2<<<dim3(NN / 256, NSEG), 256>>>(G, H);
    build_m_kernel<<<dim3(NN / 32, NN / 32), dim3(32, 8)>>>();
    gemm_mma<<<dim3(NN / BN, BB / BM), 512, DSMEM>>>(out);
}